// round 1
// baseline (speedup 1.0000x reference)
#include <cuda_runtime.h>
#include <math.h>

#define NN 50000
#define EE 800000
#define RR 8
#define BB 4

// ---------------- scratch (device globals; no allocation) ----------------
__device__ float g_x1[NN * 64];                 // after RGCN1 + relu
__device__ float g_x2[NN * 128];                // after GAT1 (concat)
__device__ float g_x3[NN * 32];                 // after RGCN2 + relu
__device__ float g_h[NN * 128];                 // GAT h features (reused)
__device__ float g_sums[(size_t)NN * RR * 128]; // RGCN per-(node,rel) sums (max in=128)
__device__ int   g_cnt[NN * RR];                // per-(node,rel) edge counts (shared by both RGCN layers)
__device__ float g_al[NN * 8];                  // [n][0..3]=al_src, [n][4..7]=al_dst (H=4)
__device__ float g_acc[NN * 128];               // GAT weighted-message accumulator
__device__ float g_z[NN * 4];                   // GAT softmax denominators

// ---------------- utility ----------------
__global__ void zero_kernel(float4* __restrict__ p, int n4) {
    int i = blockIdx.x * blockDim.x + threadIdx.x;
    if (i < n4) p[i] = make_float4(0.f, 0.f, 0.f, 0.f);
}

__global__ void count_kernel(const int* __restrict__ dst, const int* __restrict__ et) {
    int e = blockIdx.x * blockDim.x + threadIdx.x;
    if (e < EE) atomicAdd(&g_cnt[dst[e] * RR + et[e]], 1);
}

// ---------------- RGCN ----------------
// Edge scatter: sums[(dst*R+etype)*IN + c] += x[src*IN + c]
template <int IN>
__global__ void rgcn_scatter(const float* __restrict__ x, const int* __restrict__ src,
                             const int* __restrict__ dst, const int* __restrict__ et) {
    const int CH = IN / 4;
    int idx = blockIdx.x * blockDim.x + threadIdx.x;
    if (idx >= EE * CH) return;
    int e = idx / CH;
    int c = (idx - e * CH) * 4;
    int s = src[e];
    float4 v = *(const float4*)(x + (size_t)s * IN + c);
    float* b = g_sums + ((size_t)dst[e] * RR + et[e]) * IN + c;
    atomicAdd(b + 0, v.x);
    atomicAdd(b + 1, v.y);
    atomicAdd(b + 2, v.z);
    atomicAdd(b + 3, v.w);
}

// Node phase: out[n,o] = sum_b (sum_r comp[r,b]*mean_r[n]) @ basis_b + x[n]@root + bias
template <int IN, int OUT, bool RELU>
__global__ void rgcn_node(const float* __restrict__ x, const float* __restrict__ basis,
                          const float* __restrict__ comp, const float* __restrict__ root,
                          const float* __restrict__ bias, float* __restrict__ out) {
    __shared__ float xsh[IN];
    __shared__ float zsh[BB * IN];
    __shared__ float invc[RR];
    __shared__ float compsh[RR * BB];
    int t = threadIdx.x;  // OUT threads
    if (t < RR * BB) compsh[t] = comp[t];
    for (int n = blockIdx.x; n < NN; n += gridDim.x) {
        if (t < RR) {
            int c = g_cnt[n * RR + t];
            invc[t] = 1.f / fmaxf((float)c, 1.f);
        }
        for (int i = t; i < IN; i += OUT) xsh[i] = x[(size_t)n * IN + i];
        __syncthreads();
        const float* sb = g_sums + (size_t)n * RR * IN;
        for (int idx = t; idx < BB * IN; idx += OUT) {
            int b = idx / IN;
            int i = idx - b * IN;
            float a = 0.f;
#pragma unroll
            for (int r = 0; r < RR; r++) a += compsh[r * BB + b] * invc[r] * sb[r * IN + i];
            zsh[idx] = a;
        }
        __syncthreads();
        float a = bias[t];
#pragma unroll 4
        for (int k = 0; k < BB * IN; k++) a += zsh[k] * basis[k * OUT + t];
#pragma unroll 4
        for (int i = 0; i < IN; i++) a += xsh[i] * root[i * OUT + t];
        if (RELU) a = fmaxf(a, 0.f);
        out[(size_t)n * OUT + t] = a;
        __syncthreads();
    }
}

// ---------------- GAT ----------------
// Node phase: h = x @ W, al_src/al_dst per head
template <int IN, int H, int C>
__global__ void gat_node(const float* __restrict__ x, const float* __restrict__ w,
                         const float* __restrict__ asrc, const float* __restrict__ adst) {
    const int OUT = H * C;
    __shared__ float xsh[IN];
    __shared__ float hsh[OUT];
    int t = threadIdx.x;  // OUT threads
    for (int n = blockIdx.x; n < NN; n += gridDim.x) {
        for (int i = t; i < IN; i += OUT) xsh[i] = x[(size_t)n * IN + i];
        __syncthreads();
        float a = 0.f;
#pragma unroll 4
        for (int i = 0; i < IN; i++) a += xsh[i] * w[i * OUT + t];
        hsh[t] = a;
        g_h[(size_t)n * OUT + t] = a;
        __syncthreads();
        if (t < 2 * H) {
            int hh = (t < H) ? t : t - H;
            const float* av = (t < H) ? asrc : adst;
            float s = 0.f;
#pragma unroll
            for (int c = 0; c < C; c++) s += hsh[hh * C + c] * av[hh * C + c];
            g_al[n * 2 * H + t] = s;  // [0..H) = src, [H..2H) = dst
        }
        __syncthreads();
    }
}

// Edge phase: unnormalized softmax accumulate (incl. self loops)
template <int H, int C>
__global__ void gat_edge(const int* __restrict__ src, const int* __restrict__ dst) {
    int idx = blockIdx.x * blockDim.x + threadIdx.x;
    if (idx >= (EE + NN) * H) return;
    int e = idx / H;
    int h = idx - e * H;
    int s, d;
    if (e < EE) { s = src[e]; d = dst[e]; }
    else        { s = e - EE; d = s; }
    float v = g_al[s * 2 * H + h] + g_al[d * 2 * H + H + h];
    v = v > 0.f ? v : 0.2f * v;  // leaky relu, slope 0.2
    float ev = __expf(v);
    atomicAdd(&g_z[d * H + h], ev);
    const float4* hp = (const float4*)(g_h + ((size_t)s * H + h) * C);
    float* ap = g_acc + ((size_t)d * H + h) * C;
#pragma unroll
    for (int c = 0; c < C / 4; c++) {
        float4 hv = hp[c];
        atomicAdd(ap + 4 * c + 0, ev * hv.x);
        atomicAdd(ap + 4 * c + 1, ev * hv.y);
        atomicAdd(ap + 4 * c + 2, ev * hv.z);
        atomicAdd(ap + 4 * c + 3, ev * hv.w);
    }
}

template <int H, int C>
__global__ void gat_final_concat(const float* __restrict__ bias, float* __restrict__ out) {
    int idx = blockIdx.x * blockDim.x + threadIdx.x;
    if (idx >= NN * H * C) return;
    int n = idx / (H * C);
    int o = idx - n * (H * C);
    int h = o / C;
    out[idx] = g_acc[idx] / g_z[n * H + h] + bias[o];
}

template <int H, int C>
__global__ void gat_final_mean_tanh(const float* __restrict__ bias, float* __restrict__ out) {
    int idx = blockIdx.x * blockDim.x + threadIdx.x;
    if (idx >= NN * C) return;
    int n = idx / C;
    int c = idx - n * C;
    float s = 0.f;
#pragma unroll
    for (int h = 0; h < H; h++) s += g_acc[(n * H + h) * C + c] / g_z[n * H + h];
    s = s * (1.f / H) + bias[c];
    s = fmaxf(s, 0.f);   // relu after GAT2
    out[idx] = tanhf(s); // final tanh
}

// ---------------- launch ----------------
extern "C" void kernel_launch(void* const* d_in, const int* in_sizes, int n_in,
                              void* d_out, int out_size) {
    const float* x      = (const float*)d_in[0];
    const int*   ei     = (const int*)d_in[1];
    const int*   et     = (const int*)d_in[2];
    const float* basis1 = (const float*)d_in[3];
    const float* comp1  = (const float*)d_in[4];
    const float* root1  = (const float*)d_in[5];
    const float* brg1   = (const float*)d_in[6];
    const float* wg1    = (const float*)d_in[7];
    const float* asrc1  = (const float*)d_in[8];
    const float* adst1  = (const float*)d_in[9];
    const float* bg1    = (const float*)d_in[10];
    const float* basis2 = (const float*)d_in[11];
    const float* comp2  = (const float*)d_in[12];
    const float* root2  = (const float*)d_in[13];
    const float* brg2   = (const float*)d_in[14];
    const float* wg2    = (const float*)d_in[15];
    const float* asrc2  = (const float*)d_in[16];
    const float* adst2  = (const float*)d_in[17];
    const float* bg2    = (const float*)d_in[18];
    float* out = (float*)d_out;
    const int* src = ei;
    const int* dst = ei + EE;

    float *p_sums, *p_acc, *p_z, *p_x1, *p_x2, *p_x3;
    int* p_cnt;
    cudaGetSymbolAddress((void**)&p_sums, g_sums);
    cudaGetSymbolAddress((void**)&p_cnt, g_cnt);
    cudaGetSymbolAddress((void**)&p_acc, g_acc);
    cudaGetSymbolAddress((void**)&p_z, g_z);
    cudaGetSymbolAddress((void**)&p_x1, g_x1);
    cudaGetSymbolAddress((void**)&p_x2, g_x2);
    cudaGetSymbolAddress((void**)&p_x3, g_x3);

    auto zero = [](void* p, size_t floats) {
        int n4 = (int)(floats / 4);
        zero_kernel<<<(n4 + 255) / 256, 256>>>((float4*)p, n4);
    };

    // counts (shared by both RGCN layers)
    zero(p_cnt, (size_t)NN * RR);
    count_kernel<<<(EE + 255) / 256, 256>>>(dst, et);

    // ---- RGCN 1: 64 -> 64, relu ----
    zero(p_sums, (size_t)NN * RR * 64);
    rgcn_scatter<64><<<(EE * 16 + 255) / 256, 256>>>(x, src, dst, et);
    rgcn_node<64, 64, true><<<2048, 64>>>(x, basis1, comp1, root1, brg1, p_x1);

    // ---- GAT 1: 64 -> 4x32 concat (no activation) ----
    gat_node<64, 4, 32><<<2048, 128>>>(p_x1, wg1, asrc1, adst1);
    zero(p_acc, (size_t)NN * 128);
    zero(p_z, (size_t)NN * 4);
    gat_edge<4, 32><<<((EE + NN) * 4 + 255) / 256, 256>>>(src, dst);
    gat_final_concat<4, 32><<<(NN * 128 + 255) / 256, 256>>>(bg1, p_x2);

    // ---- RGCN 2: 128 -> 32, relu ----
    zero(p_sums, (size_t)NN * RR * 128);
    rgcn_scatter<128><<<(EE * 32 + 255) / 256, 256>>>(p_x2, src, dst, et);
    rgcn_node<128, 32, true><<<2048, 32>>>(p_x2, basis2, comp2, root2, brg2, p_x3);

    // ---- GAT 2: 32 -> 4x16 mean heads, relu, tanh ----
    gat_node<32, 4, 16><<<2048, 64>>>(p_x3, wg2, asrc2, adst2);
    zero(p_acc, (size_t)NN * 64);
    zero(p_z, (size_t)NN * 4);
    gat_edge<4, 16><<<((EE + NN) * 4 + 255) / 256, 256>>>(src, dst);
    gat_final_mean_tanh<4, 16><<<(NN * 16 + 255) / 256, 256>>>(bg2, out);
}

// round 2
// speedup vs baseline: 2.2624x; 2.2624x over previous
#include <cuda_runtime.h>
#include <math.h>

#define NN 50000
#define EE 800000
#define RR 8
#define BB 4

// ---------------- scratch (device globals; no allocation) ----------------
__device__ float g_x1[NN * 64];     // after RGCN1 + relu
__device__ float g_x2[NN * 128];    // after GAT1 (concat)
__device__ float g_x3[NN * 32];     // after RGCN2 + relu
__device__ float g_h[NN * 128];     // GAT transformed features
__device__ float g_al[NN * 8];      // [n][0..3]=al_src, [n][4..7]=al_dst (H=4)
__device__ int   g_cnt[NN * RR];    // per-(node,relation) in-degree
__device__ int   g_row_off[NN + 1]; // CSR offsets by dst
__device__ int   g_cursor[NN];      // fill cursors
__device__ int   g_adj[EE];         // packed: src | (etype<<16)   (NN < 65536)

// ---------------- CSR build ----------------
__global__ void zero_int(int* __restrict__ p, int n) {
    int i = blockIdx.x * blockDim.x + threadIdx.x;
    if (i < n) p[i] = 0;
}

__global__ void hist_kernel(const int* __restrict__ dst, const int* __restrict__ et) {
    int e = blockIdx.x * blockDim.x + threadIdx.x;
    if (e < EE) atomicAdd(&g_cnt[dst[e] * RR + et[e]], 1);
}

// single-block exclusive scan over node degrees (degree = sum of 8 relation counts)
__global__ void scan_kernel() {
    __shared__ int sh[1024];
    __shared__ int s_carry;
    int t = threadIdx.x;
    if (t == 0) s_carry = 0;
    __syncthreads();
    for (int base = 0; base < NN; base += 1024) {
        int i = base + t;
        int v = 0;
        if (i < NN) {
#pragma unroll
            for (int r = 0; r < RR; r++) v += g_cnt[i * RR + r];
        }
        int carry = s_carry;
        int val = v;
        sh[t] = val;
        __syncthreads();
        for (int d = 1; d < 1024; d <<= 1) {
            int add = (t >= d) ? sh[t - d] : 0;
            __syncthreads();
            val += add;
            sh[t] = val;
            __syncthreads();
        }
        if (i < NN) {
            g_row_off[i] = carry + val - v;  // exclusive
            g_cursor[i]  = carry + val - v;
        }
        __syncthreads();
        if (t == 1023) s_carry = carry + val;
        __syncthreads();
    }
    if (t == 0) g_row_off[NN] = s_carry;
}

__global__ void fill_kernel(const int* __restrict__ src, const int* __restrict__ dst,
                            const int* __restrict__ et) {
    int e = blockIdx.x * blockDim.x + threadIdx.x;
    if (e < EE) {
        int d = dst[e];
        int pos = atomicAdd(&g_cursor[d], 1);
        g_adj[pos] = src[e] | (et[e] << 16);
    }
}

// ---------------- RGCN: fused gather + basis GEMM ----------------
// one block of IN threads per node
template <int IN, int OUT>
__global__ void rgcn_gather(const float* __restrict__ x, const float* __restrict__ basis,
                            const float* __restrict__ comp, const float* __restrict__ root,
                            const float* __restrict__ bias, float* __restrict__ out) {
    const int PART = IN / OUT;
    __shared__ float zsh[BB * IN];
    __shared__ float xsh[IN];
    __shared__ float red[IN];
    __shared__ float invc[RR];
    __shared__ float compsh[RR * BB];
    int n = blockIdx.x;
    int t = threadIdx.x;
    if (t < RR * BB) compsh[t] = comp[t];
    if (t < RR) invc[t] = 1.f / fmaxf((float)g_cnt[n * RR + t], 1.f);

    float acc[RR];
#pragma unroll
    for (int r = 0; r < RR; r++) acc[r] = 0.f;

    int k0 = g_row_off[n], k1 = g_row_off[n + 1];
#pragma unroll 4
    for (int k = k0; k < k1; k++) {
        int v = g_adj[k];
        int s = v & 0xFFFF;
        int r = v >> 16;
        float xv = __ldg(x + (size_t)s * IN + t);
#pragma unroll
        for (int rr = 0; rr < RR; rr++) acc[rr] += (rr == r) ? xv : 0.f;
    }
    xsh[t] = x[(size_t)n * IN + t];
    __syncthreads();

#pragma unroll
    for (int b = 0; b < BB; b++) {
        float a = 0.f;
#pragma unroll
        for (int r = 0; r < RR; r++) a += compsh[r * BB + b] * invc[r] * acc[r];
        zsh[b * IN + t] = a;
    }
    __syncthreads();

    int o = t % OUT;
    int p = t / OUT;
    float a = 0.f;
    for (int k = p; k < BB * IN; k += PART) a += zsh[k] * __ldg(basis + k * OUT + o);
    for (int k = p; k < IN; k += PART) a += xsh[k] * __ldg(root + k * OUT + o);
    if (PART == 1) {
        a += bias[o];
        out[(size_t)n * OUT + o] = fmaxf(a, 0.f);
    } else {
        red[t] = a;
        __syncthreads();
        if (t < OUT) {
            float s = bias[t];
#pragma unroll
            for (int pp = 0; pp < PART; pp++) s += red[pp * OUT + t];
            out[(size_t)n * OUT + t] = fmaxf(s, 0.f);
        }
    }
}

// ---------------- GAT node phase: h = x @ W, attention logits ----------------
template <int IN, int H, int C>
__global__ void gat_node(const float* __restrict__ x, const float* __restrict__ w,
                         const float* __restrict__ asrc, const float* __restrict__ adst) {
    const int OUT = H * C;
    __shared__ float xsh[IN];
    __shared__ float hsh[OUT];
    int n = blockIdx.x;
    int t = threadIdx.x;
    for (int i = t; i < IN; i += OUT) xsh[i] = x[(size_t)n * IN + i];
    __syncthreads();
    float a = 0.f;
#pragma unroll 4
    for (int i = 0; i < IN; i++) a += xsh[i] * w[i * OUT + t];
    hsh[t] = a;
    g_h[(size_t)n * OUT + t] = a;
    __syncthreads();
    if (t < 2 * H) {
        int hh = (t < H) ? t : t - H;
        const float* av = (t < H) ? asrc : adst;
        float s = 0.f;
#pragma unroll
        for (int c = 0; c < C; c++) s += hsh[hh * C + c] * av[hh * C + c];
        g_al[n * 2 * H + t] = s;
    }
}

// ---------------- GAT edge gather (softmax normalized in-register) ----------------
template <int H, int C>
__device__ __forceinline__ float gat_ev(int s, int h, float aldst, int lane, int leader) {
    float tmp = 0.f;
    if (lane == leader) {
        float v = g_al[s * 8 + h] + aldst;
        v = v > 0.f ? v : 0.2f * v;
        tmp = __expf(v);
    }
    return __shfl_sync(0xffffffffu, tmp, leader);
}

template <int H, int C>
__global__ void gat_gather_concat(const float* __restrict__ bias, float* __restrict__ out) {
    const int HC = H * C;
    int n = blockIdx.x;
    int t = threadIdx.x;
    int h = t / C;
    int lane = t & 31;
    int leader = lane & ~(C - 1);
    float aldst = g_al[n * 8 + 4 + h];
    float acc = 0.f, z = 0.f;
    int k0 = g_row_off[n], k1 = g_row_off[n + 1];
#pragma unroll 2
    for (int k = k0; k < k1; k++) {
        int s = g_adj[k] & 0xFFFF;
        float ev = gat_ev<H, C>(s, h, aldst, lane, leader);
        z += ev;
        acc += ev * __ldg(g_h + (size_t)s * HC + t);
    }
    {   // self loop
        float ev = gat_ev<H, C>(n, h, aldst, lane, leader);
        z += ev;
        acc += ev * g_h[(size_t)n * HC + t];
    }
    out[(size_t)n * HC + t] = acc / z + bias[t];
}

template <int H, int C>
__global__ void gat_gather_mean_tanh(const float* __restrict__ bias, float* __restrict__ out) {
    const int HC = H * C;
    __shared__ float sh[HC];
    int n = blockIdx.x;
    int t = threadIdx.x;
    int h = t / C;
    int lane = t & 31;
    int leader = lane & ~(C - 1);
    float aldst = g_al[n * 8 + 4 + h];
    float acc = 0.f, z = 0.f;
    int k0 = g_row_off[n], k1 = g_row_off[n + 1];
#pragma unroll 2
    for (int k = k0; k < k1; k++) {
        int s = g_adj[k] & 0xFFFF;
        float ev = gat_ev<H, C>(s, h, aldst, lane, leader);
        z += ev;
        acc += ev * __ldg(g_h + (size_t)s * HC + t);
    }
    {   // self loop
        float ev = gat_ev<H, C>(n, h, aldst, lane, leader);
        z += ev;
        acc += ev * g_h[(size_t)n * HC + t];
    }
    sh[t] = acc / z;
    __syncthreads();
    if (t < C) {
        float s = 0.f;
#pragma unroll
        for (int hh = 0; hh < H; hh++) s += sh[hh * C + t];
        s = s * (1.f / H) + bias[t];
        s = fmaxf(s, 0.f);
        out[(size_t)n * C + t] = tanhf(s);
    }
}

// ---------------- launch ----------------
extern "C" void kernel_launch(void* const* d_in, const int* in_sizes, int n_in,
                              void* d_out, int out_size) {
    const float* x      = (const float*)d_in[0];
    const int*   ei     = (const int*)d_in[1];
    const int*   et     = (const int*)d_in[2];
    const float* basis1 = (const float*)d_in[3];
    const float* comp1  = (const float*)d_in[4];
    const float* root1  = (const float*)d_in[5];
    const float* brg1   = (const float*)d_in[6];
    const float* wg1    = (const float*)d_in[7];
    const float* asrc1  = (const float*)d_in[8];
    const float* adst1  = (const float*)d_in[9];
    const float* bg1    = (const float*)d_in[10];
    const float* basis2 = (const float*)d_in[11];
    const float* comp2  = (const float*)d_in[12];
    const float* root2  = (const float*)d_in[13];
    const float* brg2   = (const float*)d_in[14];
    const float* wg2    = (const float*)d_in[15];
    const float* asrc2  = (const float*)d_in[16];
    const float* adst2  = (const float*)d_in[17];
    const float* bg2    = (const float*)d_in[18];
    float* out = (float*)d_out;
    const int* src = ei;
    const int* dst = ei + EE;

    int* p_cnt;
    float *p_x1, *p_x2, *p_x3;
    cudaGetSymbolAddress((void**)&p_cnt, g_cnt);
    cudaGetSymbolAddress((void**)&p_x1, g_x1);
    cudaGetSymbolAddress((void**)&p_x2, g_x2);
    cudaGetSymbolAddress((void**)&p_x3, g_x3);

    // --- CSR build (shared by all layers) ---
    zero_int<<<(NN * RR + 255) / 256, 256>>>(p_cnt, NN * RR);
    hist_kernel<<<(EE + 255) / 256, 256>>>(dst, et);
    scan_kernel<<<1, 1024>>>();
    fill_kernel<<<(EE + 255) / 256, 256>>>(src, dst, et);

    // ---- RGCN 1: 64 -> 64, relu ----
    rgcn_gather<64, 64><<<NN, 64>>>(x, basis1, comp1, root1, brg1, p_x1);
    // ---- GAT 1: 64 -> 4x32 concat ----
    gat_node<64, 4, 32><<<NN, 128>>>(p_x1, wg1, asrc1, adst1);
    gat_gather_concat<4, 32><<<NN, 128>>>(bg1, p_x2);
    // ---- RGCN 2: 128 -> 32, relu ----
    rgcn_gather<128, 32><<<NN, 128>>>(p_x2, basis2, comp2, root2, brg2, p_x3);
    // ---- GAT 2: 32 -> 4x16, mean heads, relu, tanh ----
    gat_node<32, 4, 16><<<NN, 64>>>(p_x3, wg2, asrc2, adst2);
    gat_gather_mean_tanh<4, 16><<<NN, 64>>>(bg2, out);
}

// round 3
// speedup vs baseline: 3.1822x; 1.4065x over previous
#include <cuda_runtime.h>
#include <math.h>

#define NN 50000
#define EE 800000
#define RR 8
#define BB 4
#define NB ((NN + 255) / 256)

// ---------------- scratch (device globals; no allocation) ----------------
__device__ float g_x1[NN * 64];     // after RGCN1 + relu
__device__ float g_x2[NN * 128];    // after GAT1 (concat)
__device__ float g_x3[NN * 32];     // after RGCN2 + relu
__device__ float g_h[NN * 128];     // GAT transformed features
__device__ float g_al[NN * 8];      // [n][0..3]=al_src, [n][4..7]=al_dst (H=4)
__device__ int   g_cnt[NN * RR];    // per-(node,relation) in-degree
__device__ int   g_row_off[NN + 1]; // CSR offsets by dst
__device__ int   g_cursor[NN];      // fill cursors
__device__ int   g_adj[EE];         // packed: src | (etype<<16)
__device__ int   g_pos[EE];         // CSR slot of edge e
__device__ float g_ev[(size_t)EE * 4]; // per-edge, per-head exp(leakyrelu(...)), CSR order
__device__ int   g_nodescan[NN];
__device__ int   g_blocksum[NB];
__device__ int   g_blockoff[NB];

// ---------------- CSR build ----------------
__global__ void zero_int(int* __restrict__ p, int n) {
    int i = blockIdx.x * blockDim.x + threadIdx.x;
    if (i < n) p[i] = 0;
}

__global__ void hist_kernel(const int* __restrict__ dst, const int* __restrict__ et) {
    int e = blockIdx.x * blockDim.x + threadIdx.x;
    if (e < EE) atomicAdd(&g_cnt[dst[e] * RR + et[e]], 1);
}

__global__ void scanA() {
    __shared__ int sh[256];
    int t = threadIdx.x;
    int n = blockIdx.x * 256 + t;
    int deg = 0;
    if (n < NN) {
#pragma unroll
        for (int r = 0; r < RR; r++) deg += g_cnt[n * RR + r];
    }
    int val = deg;
    sh[t] = val;
    __syncthreads();
    for (int d = 1; d < 256; d <<= 1) {
        int a = (t >= d) ? sh[t - d] : 0;
        __syncthreads();
        val += a;
        sh[t] = val;
        __syncthreads();
    }
    if (n < NN) g_nodescan[n] = val - deg;  // exclusive within block
    if (t == 255) g_blocksum[blockIdx.x] = val;
}

__global__ void scanB() {
    __shared__ int sh[256];
    int t = threadIdx.x;
    int own = (t < NB) ? g_blocksum[t] : 0;
    int val = own;
    sh[t] = val;
    __syncthreads();
    for (int d = 1; d < 256; d <<= 1) {
        int a = (t >= d) ? sh[t - d] : 0;
        __syncthreads();
        val += a;
        sh[t] = val;
        __syncthreads();
    }
    if (t < NB) g_blockoff[t] = val - own;
    if (t == NB - 1) g_row_off[NN] = val;
}

__global__ void scanC() {
    int n = blockIdx.x * 256 + threadIdx.x;
    if (n < NN) {
        int off = g_blockoff[blockIdx.x] + g_nodescan[n];
        g_row_off[n] = off;
        g_cursor[n] = off;
    }
}

__global__ void fill_kernel(const int* __restrict__ src, const int* __restrict__ dst,
                            const int* __restrict__ et) {
    int e = blockIdx.x * blockDim.x + threadIdx.x;
    if (e < EE) {
        int d = dst[e];
        int pos = atomicAdd(&g_cursor[d], 1);
        g_adj[pos] = src[e] | (et[e] << 16);
        g_pos[e] = pos;
    }
}

// ---------------- RGCN: fused gather (B-space) + basis GEMM ----------------
template <int IN, int OUT>
__global__ __launch_bounds__(IN) void rgcn_gather(
    const float* __restrict__ x, const float* __restrict__ basis,
    const float* __restrict__ comp, const float* __restrict__ root,
    const float* __restrict__ bias, float* __restrict__ out) {
    const int PART = IN / OUT;
    __shared__ float zsh[BB * IN];
    __shared__ float xsh[IN];
    __shared__ float red[IN];
    __shared__ float wsh[RR * BB];  // comp[r][b] * invc[r]
    int n = blockIdx.x;
    int t = threadIdx.x;
    if (t < RR) {
        float ic = 1.f / fmaxf((float)g_cnt[n * RR + t], 1.f);
#pragma unroll
        for (int b = 0; b < BB; b++) wsh[t * BB + b] = comp[t * BB + b] * ic;
    }
    xsh[t] = x[(size_t)n * IN + t];
    __syncthreads();

    float acc0 = 0.f, acc1 = 0.f, acc2 = 0.f, acc3 = 0.f;
    int k0 = g_row_off[n], k1 = g_row_off[n + 1];
    int k = k0;
    for (; k + 4 <= k1; k += 4) {
        int v0 = g_adj[k + 0], v1 = g_adj[k + 1], v2 = g_adj[k + 2], v3 = g_adj[k + 3];
        float a0 = __ldg(x + (size_t)(v0 & 0xFFFF) * IN + t);
        float a1 = __ldg(x + (size_t)(v1 & 0xFFFF) * IN + t);
        float a2 = __ldg(x + (size_t)(v2 & 0xFFFF) * IN + t);
        float a3 = __ldg(x + (size_t)(v3 & 0xFFFF) * IN + t);
        const float* w0 = wsh + (v0 >> 16) * BB;
        const float* w1 = wsh + (v1 >> 16) * BB;
        const float* w2 = wsh + (v2 >> 16) * BB;
        const float* w3 = wsh + (v3 >> 16) * BB;
        acc0 += w0[0] * a0 + w1[0] * a1 + w2[0] * a2 + w3[0] * a3;
        acc1 += w0[1] * a0 + w1[1] * a1 + w2[1] * a2 + w3[1] * a3;
        acc2 += w0[2] * a0 + w1[2] * a1 + w2[2] * a2 + w3[2] * a3;
        acc3 += w0[3] * a0 + w1[3] * a1 + w2[3] * a2 + w3[3] * a3;
    }
    for (; k < k1; k++) {
        int v = g_adj[k];
        float a = __ldg(x + (size_t)(v & 0xFFFF) * IN + t);
        const float* w = wsh + (v >> 16) * BB;
        acc0 += w[0] * a;
        acc1 += w[1] * a;
        acc2 += w[2] * a;
        acc3 += w[3] * a;
    }
    zsh[0 * IN + t] = acc0;
    zsh[1 * IN + t] = acc1;
    zsh[2 * IN + t] = acc2;
    zsh[3 * IN + t] = acc3;
    __syncthreads();

    int o = t % OUT;
    int p = t / OUT;
    float a = 0.f;
    for (int kk = p; kk < BB * IN; kk += PART) a += zsh[kk] * __ldg(basis + kk * OUT + o);
    for (int kk = p; kk < IN; kk += PART) a += xsh[kk] * __ldg(root + kk * OUT + o);
    if (PART == 1) {
        a += bias[o];
        out[(size_t)n * OUT + o] = fmaxf(a, 0.f);
    } else {
        red[t] = a;
        __syncthreads();
        if (t < OUT) {
            float s = bias[t];
#pragma unroll
            for (int pp = 0; pp < PART; pp++) s += red[pp * OUT + t];
            out[(size_t)n * OUT + t] = fmaxf(s, 0.f);
        }
    }
}

// ---------------- GAT node phase: h = x @ W, attention logits ----------------
template <int IN, int H, int C>
__global__ __launch_bounds__(H * C) void gat_node(
    const float* __restrict__ x, const float* __restrict__ w,
    const float* __restrict__ asrc, const float* __restrict__ adst) {
    const int OUT = H * C;
    __shared__ float xsh[IN];
    __shared__ float hsh[OUT];
    int n = blockIdx.x;
    int t = threadIdx.x;
    for (int i = t; i < IN; i += OUT) xsh[i] = x[(size_t)n * IN + i];
    __syncthreads();
    float a = 0.f;
#pragma unroll 4
    for (int i = 0; i < IN; i++) a += xsh[i] * w[i * OUT + t];
    hsh[t] = a;
    g_h[(size_t)n * OUT + t] = a;
    __syncthreads();
    if (t < 2 * H) {
        int hh = (t < H) ? t : t - H;
        const float* av = (t < H) ? asrc : adst;
        float s = 0.f;
#pragma unroll
        for (int c = 0; c < C; c++) s += hsh[hh * C + c] * av[hh * C + c];
        g_al[n * 2 * H + t] = s;
    }
}

// ---------------- per-edge softmax numerators (edge-parallel, high MLP) ----------------
__device__ __forceinline__ float lrexp(float v) {
    v = v > 0.f ? v : 0.2f * v;
    return __expf(v);
}

__global__ void ev_kernel(const int* __restrict__ src, const int* __restrict__ dst) {
    int e = blockIdx.x * blockDim.x + threadIdx.x;
    if (e >= EE) return;
    int s = src[e], d = dst[e], pos = g_pos[e];
    float4 as = *(const float4*)(g_al + (size_t)s * 8);
    float4 ad = *(const float4*)(g_al + (size_t)d * 8 + 4);
    float4 ev;
    ev.x = lrexp(as.x + ad.x);
    ev.y = lrexp(as.y + ad.y);
    ev.z = lrexp(as.z + ad.z);
    ev.w = lrexp(as.w + ad.w);
    *(float4*)(g_ev + (size_t)pos * 4) = ev;
}

// ---------------- GAT edge gather (streams precomputed ev) ----------------
template <int H, int C>
__global__ __launch_bounds__(H * C) void gat_gather_concat(
    const float* __restrict__ bias, float* __restrict__ out) {
    const int HC = H * C;
    int n = blockIdx.x;
    int t = threadIdx.x;
    int h = t / C;
    float acc = 0.f, z = 0.f;
    int k0 = g_row_off[n], k1 = g_row_off[n + 1];
    int k = k0;
    for (; k + 4 <= k1; k += 4) {
        int s0 = g_adj[k + 0] & 0xFFFF, s1 = g_adj[k + 1] & 0xFFFF;
        int s2 = g_adj[k + 2] & 0xFFFF, s3 = g_adj[k + 3] & 0xFFFF;
        float e0 = g_ev[(size_t)(k + 0) * 4 + h], e1 = g_ev[(size_t)(k + 1) * 4 + h];
        float e2 = g_ev[(size_t)(k + 2) * 4 + h], e3 = g_ev[(size_t)(k + 3) * 4 + h];
        float h0 = __ldg(g_h + (size_t)s0 * HC + t);
        float h1 = __ldg(g_h + (size_t)s1 * HC + t);
        float h2 = __ldg(g_h + (size_t)s2 * HC + t);
        float h3 = __ldg(g_h + (size_t)s3 * HC + t);
        z += (e0 + e1) + (e2 + e3);
        acc += e0 * h0 + e1 * h1 + e2 * h2 + e3 * h3;
    }
    for (; k < k1; k++) {
        int s = g_adj[k] & 0xFFFF;
        float ev = g_ev[(size_t)k * 4 + h];
        z += ev;
        acc += ev * __ldg(g_h + (size_t)s * HC + t);
    }
    {   // self loop
        float ev = lrexp(g_al[(size_t)n * 8 + h] + g_al[(size_t)n * 8 + 4 + h]);
        z += ev;
        acc += ev * g_h[(size_t)n * HC + t];
    }
    out[(size_t)n * HC + t] = acc / z + bias[t];
}

template <int H, int C>
__global__ __launch_bounds__(H * C) void gat_gather_mean_tanh(
    const float* __restrict__ bias, float* __restrict__ out) {
    const int HC = H * C;
    __shared__ float sh[HC];
    int n = blockIdx.x;
    int t = threadIdx.x;
    int h = t / C;
    float acc = 0.f, z = 0.f;
    int k0 = g_row_off[n], k1 = g_row_off[n + 1];
    int k = k0;
    for (; k + 4 <= k1; k += 4) {
        int s0 = g_adj[k + 0] & 0xFFFF, s1 = g_adj[k + 1] & 0xFFFF;
        int s2 = g_adj[k + 2] & 0xFFFF, s3 = g_adj[k + 3] & 0xFFFF;
        float e0 = g_ev[(size_t)(k + 0) * 4 + h], e1 = g_ev[(size_t)(k + 1) * 4 + h];
        float e2 = g_ev[(size_t)(k + 2) * 4 + h], e3 = g_ev[(size_t)(k + 3) * 4 + h];
        float h0 = __ldg(g_h + (size_t)s0 * HC + t);
        float h1 = __ldg(g_h + (size_t)s1 * HC + t);
        float h2 = __ldg(g_h + (size_t)s2 * HC + t);
        float h3 = __ldg(g_h + (size_t)s3 * HC + t);
        z += (e0 + e1) + (e2 + e3);
        acc += e0 * h0 + e1 * h1 + e2 * h2 + e3 * h3;
    }
    for (; k < k1; k++) {
        int s = g_adj[k] & 0xFFFF;
        float ev = g_ev[(size_t)k * 4 + h];
        z += ev;
        acc += ev * __ldg(g_h + (size_t)s * HC + t);
    }
    {   // self loop
        float ev = lrexp(g_al[(size_t)n * 8 + h] + g_al[(size_t)n * 8 + 4 + h]);
        z += ev;
        acc += ev * g_h[(size_t)n * HC + t];
    }
    sh[t] = acc / z;
    __syncthreads();
    if (t < C) {
        float s = 0.f;
#pragma unroll
        for (int hh = 0; hh < H; hh++) s += sh[hh * C + t];
        s = s * (1.f / H) + bias[t];
        s = fmaxf(s, 0.f);
        out[(size_t)n * C + t] = tanhf(s);
    }
}

// ---------------- launch ----------------
extern "C" void kernel_launch(void* const* d_in, const int* in_sizes, int n_in,
                              void* d_out, int out_size) {
    const float* x      = (const float*)d_in[0];
    const int*   ei     = (const int*)d_in[1];
    const int*   et     = (const int*)d_in[2];
    const float* basis1 = (const float*)d_in[3];
    const float* comp1  = (const float*)d_in[4];
    const float* root1  = (const float*)d_in[5];
    const float* brg1   = (const float*)d_in[6];
    const float* wg1    = (const float*)d_in[7];
    const float* asrc1  = (const float*)d_in[8];
    const float* adst1  = (const float*)d_in[9];
    const float* bg1    = (const float*)d_in[10];
    const float* basis2 = (const float*)d_in[11];
    const float* comp2  = (const float*)d_in[12];
    const float* root2  = (const float*)d_in[13];
    const float* brg2   = (const float*)d_in[14];
    const float* wg2    = (const float*)d_in[15];
    const float* asrc2  = (const float*)d_in[16];
    const float* adst2  = (const float*)d_in[17];
    const float* bg2    = (const float*)d_in[18];
    float* out = (float*)d_out;
    const int* src = ei;
    const int* dst = ei + EE;

    int* p_cnt;
    float *p_x1, *p_x2, *p_x3;
    cudaGetSymbolAddress((void**)&p_cnt, g_cnt);
    cudaGetSymbolAddress((void**)&p_x1, g_x1);
    cudaGetSymbolAddress((void**)&p_x2, g_x2);
    cudaGetSymbolAddress((void**)&p_x3, g_x3);

    // --- CSR build (shared by all layers) ---
    zero_int<<<(NN * RR + 255) / 256, 256>>>(p_cnt, NN * RR);
    hist_kernel<<<(EE + 255) / 256, 256>>>(dst, et);
    scanA<<<NB, 256>>>();
    scanB<<<1, 256>>>();
    scanC<<<NB, 256>>>();
    fill_kernel<<<(EE + 255) / 256, 256>>>(src, dst, et);

    // ---- RGCN 1: 64 -> 64, relu ----
    rgcn_gather<64, 64><<<NN, 64>>>(x, basis1, comp1, root1, brg1, p_x1);
    // ---- GAT 1: 64 -> 4x32 concat ----
    gat_node<64, 4, 32><<<NN, 128>>>(p_x1, wg1, asrc1, adst1);
    ev_kernel<<<(EE + 255) / 256, 256>>>(src, dst);
    gat_gather_concat<4, 32><<<NN, 128>>>(bg1, p_x2);
    // ---- RGCN 2: 128 -> 32, relu ----
    rgcn_gather<128, 32><<<NN, 128>>>(p_x2, basis2, comp2, root2, brg2, p_x3);
    // ---- GAT 2: 32 -> 4x16, mean heads, relu, tanh ----
    gat_node<32, 4, 16><<<NN, 64>>>(p_x3, wg2, asrc2, adst2);
    ev_kernel<<<(EE + 255) / 256, 256>>>(src, dst);
    gat_gather_mean_tanh<4, 16><<<NN, 64>>>(bg2, out);
}